// round 14
// baseline (speedup 1.0000x reference)
#include <cuda_runtime.h>
#include <math.h>

// Problem constants
#define NN 16384
#define NB 64
#define NVOCAB 100
#define NL0 128
#define NH 64

// ---------------------------------------------------------------------------
// SINGLE fused kernel, grid = 64 + 32768. No scratch globals, no kernel A.
//
//  blocks [0, 64): MLP table + gather (R11-verified numerics: ascending-k
//    fma chain, serial ascending 64-add reduction). Each block computes the
//    full 100-entry vocab table; out[i] = table[z[i]] for its 256 nodes.
//    0.2% of the grid — hides under the store stream.
//
//  blocks [64, 32832): adjacency. block -> (row, half).
//    Coarse reject (3 L2-hot batch loads): sorted batch => if
//    batch[jbase] > b or batch[jbase+8191] < b the half-row is all zeros ->
//    pure 8x STG.128 __stcs loop (no sync, no math). Block-uniform branch.
//    Overlapping blocks recover the EXACT band once per block: threads 0/1
//    run lower/upper bound concurrently (14 L2-hot dependent loads each),
//    broadcast via shared, then the R9-proven chunk loop with the per-chunk
//    fine check (j0+3>=lo && j0<hi) — the check R11 showed is load-bearing
//    (removing it: DRAM% 90->63, +40us). pos/sq computed inline with the
//    exact reference rounding:
//      sq = (x*x + y*y) + z*z ;  d2 = (sq_i+sq_j) - 2*dot (ascending fma)
//
//  __stcs evict-first is MANDATORY (wall-clock A/B: wb 180.8 / stcs 151.2 /
//  stwt 153.6; single-pass ncu DRAM% inverted this ordering — trust replay
//  wall time). No __launch_bounds__ (occ 60->82% was DRAM-neutral in R12).
//
//  batch dtype auto-detect: int64 LE layout has 32-bit word [NN-1]==0 (a
//  high word); int32 layout has it == max batch (~63).
// ---------------------------------------------------------------------------
__global__ void fused_final(const void* __restrict__ batch_raw,
                            const int*  __restrict__ z,
                            const float* __restrict__ pos,
                            const float* __restrict__ emb,
                            const float* __restrict__ w1,
                            const float* __restrict__ b1,
                            const float* __restrict__ w2,
                            const float* __restrict__ b2,
                            float*  __restrict__ out,
                            float4* __restrict__ adj)
{
    const int tid = threadIdx.x;

    if (blockIdx.x < 64) {
        // ---- MLP table + gather (self-contained per block) ----
        __shared__ float sh[256];
        __shared__ float table[NVOCAB];
        const int v4 = tid >> 6;      // 0..3: vocab within round
        const int j  = tid & 63;      // hidden unit
        const float b2v = b2[0];

        for (int r = 0; r < 25; r++) {
            const int vv = r * 4 + v4;
            const float* e = emb + (size_t)vv * NL0;
            float acc = b1[j];
#pragma unroll 8
            for (int k = 0; k < NL0; k++)
                acc = fmaf(e[k], w1[k * NH + j], acc);
            // silu(x) = x * sigmoid(x)
            float s = 1.0f / (1.0f + expf(-acc));
            sh[tid] = (acc * s) * w2[j];
            __syncthreads();
            if (tid < 4) {
                const float* p = sh + tid * 64;
                float o = 0.0f;
                for (int k = 0; k < 64; k++) o += p[k];   // ascending, serial
                table[r * 4 + tid] = o + b2v;
            }
            __syncthreads();
        }
        int i = blockIdx.x * 256 + tid;
        out[i] = table[z[i]];
        return;
    }

    // ---- adjacency ----
    const int abid = blockIdx.x - 64;
    const int row  = abid >> 1;
    const int half = abid & 1;

    const int* w32 = (const int*)batch_raw;
    const long long* w64 = (const long long*)batch_raw;
    const bool is32 = (w32[NN - 1] != 0);

    const int b = is32 ? w32[row] : (int)w64[row];
    const int jbase = half * 8192;
    const int bFirst = is32 ? w32[jbase]        : (int)w64[jbase];
    const int bLast  = is32 ? w32[jbase + 8191] : (int)w64[jbase + 8191];

    const unsigned cbase = (unsigned)row * 4096u + (unsigned)half * 2048u;
    const float4 zero = make_float4(0.f, 0.f, 0.f, 0.f);

    if (bFirst > b || bLast < b) {
        // Pure zero-fill fast path: 8x coalesced STG.128, nothing else
#pragma unroll
        for (int k = 0; k < 8; k++)
            __stcs(&adj[cbase + tid + k * 256], zero);
        return;
    }

    // ---- slow path: recover exact band once per block ----
    __shared__ int s_band[2];
    if (tid < 2) {
        int lo = 0, hi = NN;
        if (tid == 0) {                 // lower_bound(b)
            while (lo < hi) {
                int m = (lo + hi) >> 1;
                int bm = is32 ? w32[m] : (int)w64[m];
                if (bm < b) lo = m + 1; else hi = m;
            }
        } else {                        // upper_bound(b)
            while (lo < hi) {
                int m = (lo + hi) >> 1;
                int bm = is32 ? w32[m] : (int)w64[m];
                if (bm <= b) lo = m + 1; else hi = m;
            }
        }
        s_band[tid] = lo;
    }
    __syncthreads();
    const int lo = s_band[0];
    const int hi = s_band[1];

    const float xi = pos[3 * row + 0];
    const float yi = pos[3 * row + 1];
    const float zi = pos[3 * row + 2];
    const float sqi = __fadd_rn(__fadd_rn(__fmul_rn(xi, xi),
                                          __fmul_rn(yi, yi)),
                                __fmul_rn(zi, zi));

#pragma unroll
    for (int k = 0; k < 8; k++) {
        const int c  = tid + k * 256;        // chunk within half-row
        const int j0 = jbase + (c << 2);     // first element of chunk
        float4 v = zero;
        if (j0 + 3 >= lo && j0 < hi) {       // fine check: ~99% of chunks skip
            float r[4];
#pragma unroll
            for (int e = 0; e < 4; e++) {
                const int jj = j0 + e;
                float val = 0.0f;
                if (jj >= lo && jj < hi && jj != row) {
                    const float xj = pos[3 * jj + 0];
                    const float yj = pos[3 * jj + 1];
                    const float zj = pos[3 * jj + 2];
                    const float sqj = __fadd_rn(__fadd_rn(__fmul_rn(xj, xj),
                                                          __fmul_rn(yj, yj)),
                                                __fmul_rn(zj, zj));
                    const float dot = fmaf(zi, zj,
                                      fmaf(yi, yj,
                                           __fmul_rn(xi, xj)));
                    const float d2 = __fsub_rn(__fadd_rn(sqi, sqj),
                                               __fmul_rn(2.0f, dot));
                    val = (d2 < 64.0f) ? 1.0f : 0.0f;
                }
                r[e] = val;
            }
            v = make_float4(r[0], r[1], r[2], r[3]);
        }
        __stcs(&adj[cbase + c], v);
    }
}

// ---------------------------------------------------------------------------
extern "C" void kernel_launch(void* const* d_in, const int* in_sizes, int n_in,
                              void* d_out, int out_size) {
    const int*   z     = (const int*)d_in[0];
    const void*  batch = d_in[1];           // int32 or int64, device-detected
    const float* pos   = (const float*)d_in[2];
    const float* emb   = (const float*)d_in[3];
    const float* w1    = (const float*)d_in[4];
    const float* b1    = (const float*)d_in[5];
    const float* w2    = (const float*)d_in[6];
    const float* b2    = (const float*)d_in[7];
    float* out = (float*)d_out;

    fused_final<<<64 + 32768, 256>>>(batch, z, pos, emb, w1, b1, w2, b2,
                                     out, (float4*)(out + NN));
}